// round 15
// baseline (speedup 1.0000x reference)
#include <cuda_runtime.h>
#include <cuda_fp16.h>
#include <cstdint>
#include <cstddef>

#define EPSV 1e-5f
#define NUSERS_MAX 100000
#define NFOODS_MAX 50000
#define ROWS_PER_JOB 512   // 4 m-tiles of 128 per GEMM job
#define GRID_CTAS 296      // 2 per SM, guaranteed co-resident

// Scratch (device globals, no allocations)
__device__ __align__(16) __half g_Uh[(size_t)NUSERS_MAX * 128];  // U*s + C
__device__ __align__(16) __half g_Fh[(size_t)NFOODS_MAX * 128];  // F*s
__device__ unsigned int g_bar = 0;   // monotonic grid barrier ticket counter

__device__ __forceinline__ uint32_t smem_u32(const void* p) {
    uint32_t a;
    asm("{ .reg .u64 t; cvta.to.shared.u64 t, %1; cvt.u32.u64 %0, t; }"
        : "=r"(a) : "l"(p));
    return a;
}

__device__ __forceinline__ void ldm_x4(uint32_t& r0, uint32_t& r1,
                                       uint32_t& r2, uint32_t& r3, uint32_t a) {
    asm volatile("ldmatrix.sync.aligned.m8n8.x4.shared.b16 {%0,%1,%2,%3}, [%4];"
                 : "=r"(r0), "=r"(r1), "=r"(r2), "=r"(r3) : "r"(a));
}

__device__ __forceinline__ void mma_f16(float d[4], uint32_t a0, uint32_t a1,
                                        uint32_t a2, uint32_t a3,
                                        uint32_t b0, uint32_t b1) {
    asm volatile(
        "mma.sync.aligned.m16n8k16.row.col.f32.f16.f16.f32 "
        "{%0,%1,%2,%3}, {%4,%5,%6,%7}, {%8,%9}, {%0,%1,%2,%3};"
        : "+f"(d[0]), "+f"(d[1]), "+f"(d[2]), "+f"(d[3])
        : "r"(a0), "r"(a1), "r"(a2), "r"(a3), "r"(b0), "r"(b1));
}

__device__ __forceinline__ int pchunk(int kc, int r) {
    return (kc & 8) | ((kc ^ r) & 7);
}

__device__ __forceinline__ void fill_a_pass(char* dst, const float* __restrict__ Z,
                                            int m0, int M, int r, int kc) {
    int pc16 = pchunk(kc, r) * 16;
    float4 lo = make_float4(0.f, 0.f, 0.f, 0.f);
    float4 hi = make_float4(0.f, 0.f, 0.f, 0.f);
    if (m0 + r < M) {
        lo = *(const float4*)(Z + (size_t)(m0 + r) * 128 + kc * 8);
        hi = *(const float4*)(Z + (size_t)(m0 + r) * 128 + kc * 8 + 4);
    }
    __half2 a0 = __floats2half2_rn(lo.x, lo.y);
    __half2 a1 = __floats2half2_rn(lo.z, lo.w);
    __half2 a2 = __floats2half2_rn(hi.x, hi.y);
    __half2 a3 = __floats2half2_rn(hi.z, hi.w);
    uint4 pa;
    pa.x = *(uint32_t*)&a0; pa.y = *(uint32_t*)&a1;
    pa.z = *(uint32_t*)&a2; pa.w = *(uint32_t*)&a3;
    *(uint4*)(dst + r * 256 + pc16) = pa;
}

__device__ __forceinline__ void tile_compute(
    float acc[2][8][4], uint32_t Acur, uint32_t Bu,
    int wr, int wc, int g, int idx)
{
#pragma unroll
    for (int mt = 0; mt < 2; mt++)
#pragma unroll
        for (int j = 0; j < 8; j++)
#pragma unroll
            for (int q = 0; q < 4; q++) acc[mt][j][q] = 0.f;

#pragma unroll
    for (int kk = 0; kk < 8; kk++) {
        uint32_t a[2][4];
#pragma unroll
        for (int mt = 0; mt < 2; mt++) {
            int ar  = wr + mt * 16 + (g & 1) * 8 + idx;
            int akc = kk * 2 + (g >> 1);
            ldm_x4(a[mt][0], a[mt][1], a[mt][2], a[mt][3],
                   Acur + ar * 256 + pchunk(akc, ar) * 16);
        }
#pragma unroll
        for (int jj = 0; jj < 4; jj++) {
            int bn  = wc + jj * 16 + (g >> 1) * 8 + idx;
            int bkc = kk * 2 + (g & 1);
            uint32_t b0, b1x, b2, b3;
            ldm_x4(b0, b1x, b2, b3, Bu + bn * 256 + pchunk(bkc, bn) * 16);
#pragma unroll
            for (int mt = 0; mt < 2; mt++) {
                mma_f16(acc[mt][2 * jj],     a[mt][0], a[mt][1], a[mt][2], a[mt][3], b0, b1x);
                mma_f16(acc[mt][2 * jj + 1], a[mt][0], a[mt][1], a[mt][2], a[mt][3], b2, b3);
            }
        }
    }
}

__device__ __forceinline__ void tile_epilogue(
    float acc[2][8][4], char* stage, __half* __restrict__ out, int m0, int M,
    const float* sS, const float* sC,
    int tid, int wr, int wc, int t, int qr)
{
#pragma unroll
    for (int mt = 0; mt < 2; mt++) {
#pragma unroll
        for (int j = 0; j < 8; j++) {
            int n0 = wc + j * 8 + 2 * t;
            int ch = (wc >> 3) + j;
            float s0 = sS[n0], s1 = sS[n0 + 1];
            float c0 = sC[n0], c1 = sC[n0 + 1];
            int r0 = wr + mt * 16 + qr;
            int r1 = r0 + 8;
            __half2 h0 = __floats2half2_rn(fmaf(acc[mt][j][0], s0, c0),
                                           fmaf(acc[mt][j][1], s1, c1));
            __half2 h1 = __floats2half2_rn(fmaf(acc[mt][j][2], s0, c0),
                                           fmaf(acc[mt][j][3], s1, c1));
            *(__half2*)(stage + r0 * 256 + ((ch ^ (r0 & 7)) * 16) + 4 * t) = h0;
            *(__half2*)(stage + r1 * 256 + ((ch ^ (r1 & 7)) * 16) + 4 * t) = h1;
        }
    }
    __syncthreads();
#pragma unroll
    for (int pass = 0; pass < 8; pass++) {
        int i   = tid + pass * 256;
        int row = i >> 4;
        int ch  = i & 15;
        uint4 v = *(uint4*)(stage + row * 256 + ((ch ^ (row & 7)) * 16));
        int gr = m0 + row;
        if (gr < M)
            *(uint4*)(out + (size_t)gr * 128 + ch * 8) = v;
    }
}

// ---------------------------------------------------------------------------
// Fused kernel: GEMM phase (grid-stride jobs) -> grid barrier -> edge phase.
// 296 CTAs, 2/SM, all co-resident (smem 64KB, regs capped by launch_bounds).
// ---------------------------------------------------------------------------
__global__ void __launch_bounds__(256, 2)
fused_kernel(const float* __restrict__ zu, int Mu,
             const float* __restrict__ zf, int Mf,
             const float* __restrict__ W1,
             const float* __restrict__ gamma, const float* __restrict__ rvar,
             const float* __restrict__ b1v, const float* __restrict__ beta,
             const float* __restrict__ rmean,
             __half* __restrict__ Uh, __half* __restrict__ Fh,
             int jobs_u, int jobs_total,
             const void* __restrict__ rowp, const void* __restrict__ colp,
             const float* __restrict__ W2, const float* __restrict__ b2,
             float* __restrict__ out, int E, int n_users, int n_foods)
{
    extern __shared__ char smem[];     // B:[0,32K) A:[32K,64K)
    char* Bb = smem;
    char* Ab = smem + 32768;
    __shared__ float sS[128];
    __shared__ float sCu[128];
    __shared__ float sCz[128];
    __shared__ __half2 sWh[64];
    __shared__ int s_is64;

    const int tid  = threadIdx.x;
    const int wrp  = tid >> 5;
    const int lane = tid & 31;

    if (tid < 128) {
        float s = gamma[tid] * rsqrtf(rvar[tid] + EPSV);
        sS[tid]  = s;
        sCu[tid] = b1v[tid] * s + beta[tid] - rmean[tid] * s;
        sCz[tid] = 0.f;
    }
    if (tid < 64) {
        float2 w2 = ((const float2*)W2)[tid];
        sWh[tid] = __floats2half2_rn(w2.x, w2.y);
    }
    if (tid < 32) {
        unsigned int v = ((const unsigned int*)rowp)[2 * tid + 1];
        unsigned int any = __ballot_sync(0xffffffffu, v != 0u);
        if (tid == 0) s_is64 = (any == 0u) ? 1 : 0;
    }
    __syncthreads();

    const int kc = tid & 15;
    const int rb = tid >> 4;
    const uint32_t Bu = smem_u32(Bb);
    const uint32_t Au = smem_u32(Ab);
    const int g   = lane >> 3;
    const int idx = lane & 7;
    const int wr  = (wrp & 3) * 32;
    const int wc  = (wrp >> 2) * 64;
    const int t   = lane & 3;
    const int qr  = lane >> 2;

    // ================= GEMM phase (grid-stride over jobs) =================
    int prev_koff = -1;
#pragma unroll 1
    for (int job = blockIdx.x; job < jobs_total; job += gridDim.x) {
        const float* Z; int M; int koff; __half* outT; const float* sC;
        int jb = job;
        if (jb < jobs_u) { Z = zu; M = Mu; koff = 0;   outT = Uh; sC = sCu; }
        else             { Z = zf; M = Mf; koff = 128; outT = Fh; sC = sCz; jb -= jobs_u; }
        const int mbase = jb * ROWS_PER_JOB;

        if (koff != prev_koff) {
            // fill B for this table
#pragma unroll
            for (int pass = 0; pass < 8; pass++) {
                int r = rb + pass * 16;
                int pc16 = pchunk(kc, r) * 16;
                float4 bl = *(const float4*)(W1 + (size_t)r * 256 + koff + kc * 8);
                float4 bh = *(const float4*)(W1 + (size_t)r * 256 + koff + kc * 8 + 4);
                __half2 b0 = __floats2half2_rn(bl.x, bl.y);
                __half2 b1h = __floats2half2_rn(bl.z, bl.w);
                __half2 b2h = __floats2half2_rn(bh.x, bh.y);
                __half2 b3 = __floats2half2_rn(bh.z, bh.w);
                uint4 pb;
                pb.x = *(uint32_t*)&b0;  pb.y = *(uint32_t*)&b1h;
                pb.z = *(uint32_t*)&b2h; pb.w = *(uint32_t*)&b3;
                *(uint4*)(Bb + r * 256 + pc16) = pb;
            }
            prev_koff = koff;
        }

        float acc[2][8][4];
#pragma unroll 1
        for (int tile = 0; tile < 4; tile++) {
            const int m0 = mbase + tile * 128;
            if (m0 >= M) break;
#pragma unroll
            for (int pass = 0; pass < 8; pass++)
                fill_a_pass(Ab, Z, m0, M, rb + pass * 16, kc);
            __syncthreads();

            tile_compute(acc, Au, Bu, wr, wc, g, idx);
            __syncthreads();

            tile_epilogue(acc, Ab, outT, m0, M, sS, sC, tid, wr, wc, t, qr);
            __syncthreads();
        }
    }

    // ================= grid barrier (all 296 CTAs co-resident) ============
    __syncthreads();
    if (tid == 0) {
        __threadfence();
        unsigned int ticket = atomicAdd(&g_bar, 1u);
        unsigned int target = (ticket / gridDim.x + 1u) * gridDim.x;
        while (atomicAdd(&g_bar, 0u) < target)
            __nanosleep(64);
    }
    __syncthreads();

    // ================= edge phase =================
    __half2 w[8];
#pragma unroll
    for (int i = 0; i < 8; i++) w[i] = sWh[(lane & 7) * 8 + i];
    const __half2 z2 = __half2half2(__ushort_as_half(0));
    const int sub = lane & 7;
    const float bias = b2[0] + 0.1f;
    const int is64 = s_is64;

    const int warp = blockIdx.x * 8 + wrp;
    const int nw = gridDim.x * 8;

    const int*       row32 = (const int*)rowp;
    const int*       col32 = (const int*)colp;
    const long long* row64 = (const long long*)rowp;
    const long long* col64 = (const long long*)colp;
    const uint4* U4 = (const uint4*)Uh;
    const uint4* F4 = (const uint4*)Fh;

    for (int base = warp * 32; base < E; base += nw * 32) {
        int myE = base + lane;
        int mi = myE < E ? myE : (E - 1);
        int ri, ci;
        if (is64) { ri = (int)row64[mi]; ci = (int)col64[mi]; }
        else      { ri = row32[mi];      ci = col32[mi]; }
        ri = min(max(ri, 0), n_users - 1);
        ci = min(max(ci, 0), n_foods - 1);

        uint4 bu0[2], bu1[2], bf0[2], bf1[2];
        {
            int rr = __shfl_sync(0xffffffffu, ri, g);
            int cc = __shfl_sync(0xffffffffu, ci, g);
            size_t ub = (size_t)rr * 16 + sub * 2;
            size_t fb = (size_t)cc * 16 + sub * 2;
            bu0[0] = U4[ub]; bu1[0] = U4[ub + 1];
            bf0[0] = F4[fb]; bf1[0] = F4[fb + 1];
        }

#pragma unroll
        for (int it = 0; it < 8; it++) {
            int cur = it & 1, nxt = cur ^ 1;
            if (it < 7) {
                int j2 = (it + 1) * 4 + g;
                int rr = __shfl_sync(0xffffffffu, ri, j2);
                int cc = __shfl_sync(0xffffffffu, ci, j2);
                size_t ub = (size_t)rr * 16 + sub * 2;
                size_t fb = (size_t)cc * 16 + sub * 2;
                bu0[nxt] = U4[ub]; bu1[nxt] = U4[ub + 1];
                bf0[nxt] = F4[fb]; bf1[nxt] = F4[fb + 1];
            }

            __half2 acc0 = z2, acc1 = z2;
#pragma unroll
            for (int q = 0; q < 4; q++) {
                uint32_t uq = (&bu0[cur].x)[q], fq = (&bf0[cur].x)[q];
                __half2 h = __hmax2(__hadd2(*(__half2*)&uq, *(__half2*)&fq), z2);
                if (q & 1) acc1 = __hfma2(h, w[q], acc1);
                else       acc0 = __hfma2(h, w[q], acc0);
            }
#pragma unroll
            for (int q = 0; q < 4; q++) {
                uint32_t uq = (&bu1[cur].x)[q], fq = (&bf1[cur].x)[q];
                __half2 h = __hmax2(__hadd2(*(__half2*)&uq, *(__half2*)&fq), z2);
                if (q & 1) acc1 = __hfma2(h, w[q + 4], acc1);
                else       acc0 = __hfma2(h, w[q + 4], acc0);
            }
            float2 dv = __half22float2(__hadd2(acc0, acc1));
            float dot = dv.x + dv.y;

            dot += __shfl_xor_sync(0xffffffffu, dot, 4);
            dot += __shfl_xor_sync(0xffffffffu, dot, 2);
            dot += __shfl_xor_sync(0xffffffffu, dot, 1);

            int e = base + it * 4 + g;
            if (sub == 0 && e < E)
                out[e] = 1.f / (1.f + __expf(-(dot + bias)));
        }
    }
}

// ---------------------------------------------------------------------------
// kernel_launch
// Inputs: z_user, z_food, row, col, W1, b1, gamma, beta, rmean, rvar, W2, b2
// ---------------------------------------------------------------------------
extern "C" void kernel_launch(void* const* d_in, const int* in_sizes, int n_in,
                              void* d_out, int out_size)
{
    const float* z_user = (const float*)d_in[0];
    const float* z_food = (const float*)d_in[1];
    const void*  row    = d_in[2];
    const void*  col    = d_in[3];
    const float* W1     = (const float*)d_in[4];
    const float* b1     = (const float*)d_in[5];
    const float* gamma  = (const float*)d_in[6];
    const float* beta   = (const float*)d_in[7];
    const float* rmean  = (const float*)d_in[8];
    const float* rvar   = (const float*)d_in[9];
    const float* W2     = (const float*)d_in[10];
    const float* b2     = (const float*)d_in[11];
    float*       out    = (float*)d_out;

    int n_users = in_sizes[0] / 128;
    int n_foods = in_sizes[1] / 128;
    int E       = in_sizes[2];
    if (n_users > NUSERS_MAX) n_users = NUSERS_MAX;
    if (n_foods > NFOODS_MAX) n_foods = NFOODS_MAX;

    __half *pU = nullptr, *pF = nullptr;
    cudaGetSymbolAddress((void**)&pU, g_Uh);
    cudaGetSymbolAddress((void**)&pF, g_Fh);

    int jobs_u = (n_users + ROWS_PER_JOB - 1) / ROWS_PER_JOB;
    int jobs_f = (n_foods + ROWS_PER_JOB - 1) / ROWS_PER_JOB;
    int smem = 65536;
    cudaFuncSetAttribute(fused_kernel, cudaFuncAttributeMaxDynamicSharedMemorySize, smem);
    fused_kernel<<<GRID_CTAS, 256, smem>>>(z_user, n_users, z_food, n_foods,
                                           W1, gamma, rvar, b1, beta, rmean,
                                           pU, pF, jobs_u, jobs_u + jobs_f,
                                           row, col, W2, b2, out,
                                           E, n_users, n_foods);
}

// round 16
// speedup vs baseline: 1.1241x; 1.1241x over previous
#include <cuda_runtime.h>
#include <cuda_fp16.h>
#include <cstdint>
#include <cstddef>

#define EPSV 1e-5f
#define NUSERS_MAX 100000
#define NFOODS_MAX 50000
#define ROWS_PER_CTA 512   // 4 m-tiles of 128

// Scratch (device globals, no allocations)
__device__ __align__(16) __half g_Uh[(size_t)NUSERS_MAX * 128];  // U*s + C
__device__ __align__(16) __half g_Fh[(size_t)NFOODS_MAX * 128];  // F*s

__device__ __forceinline__ uint32_t smem_u32(const void* p) {
    uint32_t a;
    asm("{ .reg .u64 t; cvta.to.shared.u64 t, %1; cvt.u32.u64 %0, t; }"
        : "=r"(a) : "l"(p));
    return a;
}

__device__ __forceinline__ void ldm_x4(uint32_t& r0, uint32_t& r1,
                                       uint32_t& r2, uint32_t& r3, uint32_t a) {
    asm volatile("ldmatrix.sync.aligned.m8n8.x4.shared.b16 {%0,%1,%2,%3}, [%4];"
                 : "=r"(r0), "=r"(r1), "=r"(r2), "=r"(r3) : "r"(a));
}

__device__ __forceinline__ void mma_f16(float d[4], uint32_t a0, uint32_t a1,
                                        uint32_t a2, uint32_t a3,
                                        uint32_t b0, uint32_t b1) {
    asm volatile(
        "mma.sync.aligned.m16n8k16.row.col.f32.f16.f16.f32 "
        "{%0,%1,%2,%3}, {%4,%5,%6,%7}, {%8,%9}, {%0,%1,%2,%3};"
        : "+f"(d[0]), "+f"(d[1]), "+f"(d[2]), "+f"(d[3])
        : "r"(a0), "r"(a1), "r"(a2), "r"(a3), "r"(b0), "r"(b1));
}

__device__ __forceinline__ int pchunk(int kc, int r) {
    return (kc & 8) | ((kc ^ r) & 7);
}

// Convert one (row, kc) pass of a Z tile to fp16 into buffer `dst`.
__device__ __forceinline__ void fill_a_pass(char* dst, const float* __restrict__ Z,
                                            int m0, int M, int r, int kc) {
    int pc16 = pchunk(kc, r) * 16;
    float4 lo = make_float4(0.f, 0.f, 0.f, 0.f);
    float4 hi = make_float4(0.f, 0.f, 0.f, 0.f);
    if (m0 + r < M) {
        lo = *(const float4*)(Z + (size_t)(m0 + r) * 128 + kc * 8);
        hi = *(const float4*)(Z + (size_t)(m0 + r) * 128 + kc * 8 + 4);
    }
    __half2 a0 = __floats2half2_rn(lo.x, lo.y);
    __half2 a1 = __floats2half2_rn(lo.z, lo.w);
    __half2 a2 = __floats2half2_rn(hi.x, hi.y);
    __half2 a3 = __floats2half2_rn(hi.z, hi.w);
    uint4 pa;
    pa.x = *(uint32_t*)&a0; pa.y = *(uint32_t*)&a1;
    pa.z = *(uint32_t*)&a2; pa.w = *(uint32_t*)&a3;
    *(uint4*)(dst + r * 256 + pc16) = pa;
}

// MMA over one 128x128 A buffer.
__device__ __forceinline__ void tile_compute(
    float acc[2][8][4], uint32_t Acur, uint32_t Bu,
    int wr, int wc, int g, int idx)
{
#pragma unroll
    for (int mt = 0; mt < 2; mt++)
#pragma unroll
        for (int j = 0; j < 8; j++)
#pragma unroll
            for (int q = 0; q < 4; q++) acc[mt][j][q] = 0.f;

#pragma unroll
    for (int kk = 0; kk < 8; kk++) {
        uint32_t a[2][4];
#pragma unroll
        for (int mt = 0; mt < 2; mt++) {
            int ar  = wr + mt * 16 + (g & 1) * 8 + idx;
            int akc = kk * 2 + (g >> 1);
            ldm_x4(a[mt][0], a[mt][1], a[mt][2], a[mt][3],
                   Acur + ar * 256 + pchunk(akc, ar) * 16);
        }
#pragma unroll
        for (int jj = 0; jj < 4; jj++) {
            int bn  = wc + jj * 16 + (g >> 1) * 8 + idx;
            int bkc = kk * 2 + (g & 1);
            uint32_t b0, b1x, b2, b3;
            ldm_x4(b0, b1x, b2, b3, Bu + bn * 256 + pchunk(bkc, bn) * 16);
#pragma unroll
            for (int mt = 0; mt < 2; mt++) {
                mma_f16(acc[mt][2 * jj],     a[mt][0], a[mt][1], a[mt][2], a[mt][3], b0, b1x);
                mma_f16(acc[mt][2 * jj + 1], a[mt][0], a[mt][1], a[mt][2], a[mt][3], b2, b3);
            }
        }
    }
}

// Epilogue: scale (+C), stage fp16 tile into `stage` smem, coalesced STG.
__device__ __forceinline__ void tile_epilogue(
    float acc[2][8][4], char* stage, __half* __restrict__ out, int m0, int M,
    const float* sS, const float* sC,
    int tid, int wr, int wc, int t, int qr)
{
#pragma unroll
    for (int mt = 0; mt < 2; mt++) {
#pragma unroll
        for (int j = 0; j < 8; j++) {
            int n0 = wc + j * 8 + 2 * t;
            int ch = (wc >> 3) + j;
            float s0 = sS[n0], s1 = sS[n0 + 1];
            float c0 = sC[n0], c1 = sC[n0 + 1];
            int r0 = wr + mt * 16 + qr;
            int r1 = r0 + 8;
            __half2 h0 = __floats2half2_rn(fmaf(acc[mt][j][0], s0, c0),
                                           fmaf(acc[mt][j][1], s1, c1));
            __half2 h1 = __floats2half2_rn(fmaf(acc[mt][j][2], s0, c0),
                                           fmaf(acc[mt][j][3], s1, c1));
            *(__half2*)(stage + r0 * 256 + ((ch ^ (r0 & 7)) * 16) + 4 * t) = h0;
            *(__half2*)(stage + r1 * 256 + ((ch ^ (r1 & 7)) * 16) + 4 * t) = h1;
        }
    }
    __syncthreads();
#pragma unroll
    for (int pass = 0; pass < 8; pass++) {
        int i   = tid + pass * 256;
        int row = i >> 4;
        int ch  = i & 15;
        uint4 v = *(uint4*)(stage + row * 256 + ((ch ^ (row & 7)) * 16));
        int gr = m0 + row;
        if (gr < M)
            *(uint4*)(out + (size_t)gr * 128 + ch * 8) = v;
    }
}

// ---------------------------------------------------------------------------
// fp16 HMMA GEMM: 4 m-tiles per CTA (512 rows), one W1 fill, single wave.
// Ends with griddepcontrol.launch_dependents (PDL) after all table writes.
// ---------------------------------------------------------------------------
__global__ void __launch_bounds__(256, 2)
gemm_mma(const float* __restrict__ zu, int Mu,
         const float* __restrict__ zf, int Mf,
         const float* __restrict__ W1,
         const float* __restrict__ gamma, const float* __restrict__ rvar,
         const float* __restrict__ b1, const float* __restrict__ beta,
         const float* __restrict__ rmean,
         __half* __restrict__ Uh, __half* __restrict__ Fh, int ctas_u)
{
    extern __shared__ char smem[];     // B:[0,32K) A:[32K,64K)
    char* Bb = smem;
    char* Ab = smem + 32768;
    __shared__ float sS[128];
    __shared__ float sC[128];

    int bid = blockIdx.x;
    const float* Z; int M; int koff; __half* out; bool isU;
    if (bid < ctas_u) { Z = zu; M = Mu; koff = 0;   out = Uh; isU = true; }
    else              { Z = zf; M = Mf; koff = 128; out = Fh; isU = false; bid -= ctas_u; }
    const int mbase = bid * ROWS_PER_CTA;

    const int tid  = threadIdx.x;
    const int wrp  = tid >> 5;
    const int lane = tid & 31;

    if (tid < 128) {
        float s = gamma[tid] * rsqrtf(rvar[tid] + EPSV);
        sS[tid] = s;
        sC[tid] = isU ? (b1[tid] * s + beta[tid] - rmean[tid] * s) : 0.f;
    }

    const int kc = tid & 15;
    const int rb = tid >> 4;

    // ---- fill B once ----
#pragma unroll
    for (int pass = 0; pass < 8; pass++) {
        int r = rb + pass * 16;
        int pc16 = pchunk(kc, r) * 16;
        float4 bl = *(const float4*)(W1 + (size_t)r * 256 + koff + kc * 8);
        float4 bh = *(const float4*)(W1 + (size_t)r * 256 + koff + kc * 8 + 4);
        __half2 b0 = __floats2half2_rn(bl.x, bl.y);
        __half2 b1h = __floats2half2_rn(bl.z, bl.w);
        __half2 b2 = __floats2half2_rn(bh.x, bh.y);
        __half2 b3 = __floats2half2_rn(bh.z, bh.w);
        uint4 pb;
        pb.x = *(uint32_t*)&b0; pb.y = *(uint32_t*)&b1h;
        pb.z = *(uint32_t*)&b2; pb.w = *(uint32_t*)&b3;
        *(uint4*)(Bb + r * 256 + pc16) = pb;
    }

    const uint32_t Bu = smem_u32(Bb);
    const uint32_t Au = smem_u32(Ab);
    const int g   = lane >> 3;
    const int idx = lane & 7;
    const int wr  = (wrp & 3) * 32;
    const int wc  = (wrp >> 2) * 64;
    const int t   = lane & 3;
    const int qr  = lane >> 2;

    float acc[2][8][4];

#pragma unroll 1
    for (int tile = 0; tile < 4; tile++) {
        const int m0 = mbase + tile * 128;
        if (m0 >= M) break;

#pragma unroll
        for (int pass = 0; pass < 8; pass++)
            fill_a_pass(Ab, Z, m0, M, rb + pass * 16, kc);
        __syncthreads();

        tile_compute(acc, Au, Bu, wr, wc, g, idx);
        __syncthreads();                  // MMA reads of A done

        tile_epilogue(acc, Ab, out, m0, M, sS, sC, tid, wr, wc, t, qr);
        __syncthreads();                  // stage reads done before next fill
    }

    // PDL: table writes for this CTA are done and flushed.
    __threadfence();
    asm volatile("griddepcontrol.launch_dependents;");
}

// ---------------------------------------------------------------------------
// Edge kernel (PDL consumer): prologue (W2, is64, first-batch indices) runs
// overlapped with the GEMM tail; griddepcontrol.wait before table gathers.
// 4 edges/warp (8 lanes/edge), fp16 math, batched indices, double-buffered.
// ---------------------------------------------------------------------------
__global__ void __launch_bounds__(256)
edge_kernel(const __half* __restrict__ U, const __half* __restrict__ F,
            const void* __restrict__ rowp, const void* __restrict__ colp,
            const float* __restrict__ W2, const float* __restrict__ b2,
            float* __restrict__ out, int E, int n_users, int n_foods)
{
    __shared__ __half2 sWh[64];
    __shared__ int s_is64;
    int tid = threadIdx.x;
    if (tid < 64) {
        float2 w2 = ((const float2*)W2)[tid];
        sWh[tid] = __floats2half2_rn(w2.x, w2.y);
    }
    if (tid < 32) {
        unsigned int v = ((const unsigned int*)rowp)[2 * tid + 1];
        unsigned int any = __ballot_sync(0xffffffffu, v != 0u);
        if (tid == 0) s_is64 = (any == 0u) ? 1 : 0;
    }
    __syncthreads();

    const int lane = tid & 31;
    const int sub  = lane & 7;
    const int g    = lane >> 3;

    __half2 w[8];
#pragma unroll
    for (int i = 0; i < 8; i++) w[i] = sWh[sub * 8 + i];
    const __half2 z2 = __half2half2(__ushort_as_half(0));

    const int warp = blockIdx.x * 8 + (tid >> 5);
    const int nw = gridDim.x * 8;
    const int is64 = s_is64;
    const float bias = b2[0] + 0.1f;

    const int*       row32 = (const int*)rowp;
    const int*       col32 = (const int*)colp;
    const long long* row64 = (const long long*)rowp;
    const long long* col64 = (const long long*)colp;
    const uint4* U4 = (const uint4*)U;
    const uint4* F4 = (const uint4*)F;

    bool waited = false;
    for (int base = warp * 32; base < E; base += nw * 32) {
        // batched index load (reads harness inputs only — safe pre-wait)
        int myE = base + lane;
        int mi = myE < E ? myE : (E - 1);
        int ri, ci;
        if (is64) { ri = (int)row64[mi]; ci = (int)col64[mi]; }
        else      { ri = row32[mi];      ci = col32[mi]; }
        ri = min(max(ri, 0), n_users - 1);
        ci = min(max(ci, 0), n_foods - 1);

        if (!waited) {
            // Block until the GEMM grid has signaled (tables fully written).
            asm volatile("griddepcontrol.wait;" ::: "memory");
            waited = true;
        }

        uint4 bu0[2], bu1[2], bf0[2], bf1[2];
        {
            int rr = __shfl_sync(0xffffffffu, ri, g);
            int cc = __shfl_sync(0xffffffffu, ci, g);
            size_t ub = (size_t)rr * 16 + sub * 2;
            size_t fb = (size_t)cc * 16 + sub * 2;
            bu0[0] = U4[ub]; bu1[0] = U4[ub + 1];
            bf0[0] = F4[fb]; bf1[0] = F4[fb + 1];
        }

#pragma unroll
        for (int it = 0; it < 8; it++) {
            int cur = it & 1, nxt = cur ^ 1;
            if (it < 7) {
                int j2 = (it + 1) * 4 + g;
                int rr = __shfl_sync(0xffffffffu, ri, j2);
                int cc = __shfl_sync(0xffffffffu, ci, j2);
                size_t ub = (size_t)rr * 16 + sub * 2;
                size_t fb = (size_t)cc * 16 + sub * 2;
                bu0[nxt] = U4[ub]; bu1[nxt] = U4[ub + 1];
                bf0[nxt] = F4[fb]; bf1[nxt] = F4[fb + 1];
            }

            __half2 acc0 = z2, acc1 = z2;
#pragma unroll
            for (int q = 0; q < 4; q++) {
                uint32_t uq = (&bu0[cur].x)[q], fq = (&bf0[cur].x)[q];
                __half2 h = __hmax2(__hadd2(*(__half2*)&uq, *(__half2*)&fq), z2);
                if (q & 1) acc1 = __hfma2(h, w[q], acc1);
                else       acc0 = __hfma2(h, w[q], acc0);
            }
#pragma unroll
            for (int q = 0; q < 4; q++) {
                uint32_t uq = (&bu1[cur].x)[q], fq = (&bf1[cur].x)[q];
                __half2 h = __hmax2(__hadd2(*(__half2*)&uq, *(__half2*)&fq), z2);
                if (q & 1) acc1 = __hfma2(h, w[q + 4], acc1);
                else       acc0 = __hfma2(h, w[q + 4], acc0);
            }
            float2 dv = __half22float2(__hadd2(acc0, acc1));
            float dot = dv.x + dv.y;

            dot += __shfl_xor_sync(0xffffffffu, dot, 4);
            dot += __shfl_xor_sync(0xffffffffu, dot, 2);
            dot += __shfl_xor_sync(0xffffffffu, dot, 1);

            int e = base + it * 4 + g;
            if (sub == 0 && e < E)
                out[e] = 1.f / (1.f + __expf(-(dot + bias)));
        }
    }
}

// ---------------------------------------------------------------------------
// kernel_launch
// Inputs: z_user, z_food, row, col, W1, b1, gamma, beta, rmean, rvar, W2, b2
// ---------------------------------------------------------------------------
extern "C" void kernel_launch(void* const* d_in, const int* in_sizes, int n_in,
                              void* d_out, int out_size)
{
    const float* z_user = (const float*)d_in[0];
    const float* z_food = (const float*)d_in[1];
    const void*  row    = d_in[2];
    const void*  col    = d_in[3];
    const float* W1     = (const float*)d_in[4];
    const float* b1     = (const float*)d_in[5];
    const float* gamma  = (const float*)d_in[6];
    const float* beta   = (const float*)d_in[7];
    const float* rmean  = (const float*)d_in[8];
    const float* rvar   = (const float*)d_in[9];
    const float* W2     = (const float*)d_in[10];
    const float* b2     = (const float*)d_in[11];
    float*       out    = (float*)d_out;

    int n_users = in_sizes[0] / 128;
    int n_foods = in_sizes[1] / 128;
    int E       = in_sizes[2];
    if (n_users > NUSERS_MAX) n_users = NUSERS_MAX;
    if (n_foods > NFOODS_MAX) n_foods = NFOODS_MAX;

    __half *pU = nullptr, *pF = nullptr;
    cudaGetSymbolAddress((void**)&pU, g_Uh);
    cudaGetSymbolAddress((void**)&pF, g_Fh);

    int ctas_u = (n_users + ROWS_PER_CTA - 1) / ROWS_PER_CTA;
    int ctas_f = (n_foods + ROWS_PER_CTA - 1) / ROWS_PER_CTA;
    int smem = 65536;
    cudaFuncSetAttribute(gemm_mma, cudaFuncAttributeMaxDynamicSharedMemorySize, smem);
    gemm_mma<<<ctas_u + ctas_f, 256, smem>>>(z_user, n_users, z_food, n_foods,
                                             W1, gamma, rvar, b1, beta, rmean,
                                             pU, pF, ctas_u);

    // Edge kernel with programmatic dependent launch (overlap prologue with
    // the GEMM tail). Falls back to normal serialization if unsupported.
    cudaLaunchConfig_t cfg = {};
    cfg.gridDim  = dim3(148 * 8, 1, 1);
    cfg.blockDim = dim3(256, 1, 1);
    cfg.dynamicSmemBytes = 0;
    cudaLaunchAttribute attrs[1];
    attrs[0].id = cudaLaunchAttributeProgrammaticStreamSerialization;
    attrs[0].val.programmaticStreamSerializationAllowed = 1;
    cfg.attrs = attrs;
    cfg.numAttrs = 1;
    cudaError_t err = cudaLaunchKernelEx(&cfg, edge_kernel,
                                         (const __half*)pU, (const __half*)pF,
                                         row, col, W2, b2, out,
                                         E, n_users, n_foods);
    if (err != cudaSuccess) {
        // fallback: plain launch (griddepcontrol.wait is a no-op then)
        edge_kernel<<<148 * 8, 256>>>(pU, pF, row, col, W2, b2, out,
                                      E, n_users, n_foods);
    }
}

// round 17
// speedup vs baseline: 1.1246x; 1.0005x over previous
#include <cuda_runtime.h>
#include <cuda_fp16.h>
#include <cstdint>
#include <cstddef>

#define EPSV 1e-5f
#define NUSERS_MAX 100000
#define NFOODS_MAX 50000
#define TILES_PER_CTA 8
#define ROWS_PER_CTA 1024   // 8 m-tiles of 128

// Scratch (device globals, no allocations)
__device__ __align__(16) __half g_Uh[(size_t)NUSERS_MAX * 128];  // U*s + C
__device__ __align__(16) __half g_Fh[(size_t)NFOODS_MAX * 128];  // F*s

__device__ __forceinline__ uint32_t smem_u32(const void* p) {
    uint32_t a;
    asm("{ .reg .u64 t; cvta.to.shared.u64 t, %1; cvt.u32.u64 %0, t; }"
        : "=r"(a) : "l"(p));
    return a;
}

__device__ __forceinline__ void ldm_x4(uint32_t& r0, uint32_t& r1,
                                       uint32_t& r2, uint32_t& r3, uint32_t a) {
    asm volatile("ldmatrix.sync.aligned.m8n8.x4.shared.b16 {%0,%1,%2,%3}, [%4];"
                 : "=r"(r0), "=r"(r1), "=r"(r2), "=r"(r3) : "r"(a));
}

__device__ __forceinline__ void mma_f16(float d[4], uint32_t a0, uint32_t a1,
                                        uint32_t a2, uint32_t a3,
                                        uint32_t b0, uint32_t b1) {
    asm volatile(
        "mma.sync.aligned.m16n8k16.row.col.f32.f16.f16.f32 "
        "{%0,%1,%2,%3}, {%4,%5,%6,%7}, {%8,%9}, {%0,%1,%2,%3};"
        : "+f"(d[0]), "+f"(d[1]), "+f"(d[2]), "+f"(d[3])
        : "r"(a0), "r"(a1), "r"(a2), "r"(a3), "r"(b0), "r"(b1));
}

__device__ __forceinline__ int pchunk(int kc, int r) {
    return (kc & 8) | ((kc ^ r) & 7);
}

// ---- cp.async helpers ----
__device__ __forceinline__ void cpasync16(uint32_t dst, const void* src, unsigned sz) {
    asm volatile("cp.async.cg.shared.global [%0], [%1], 16, %2;"
                 :: "r"(dst), "l"(src), "r"(sz) : "memory");
}
#define CPASYNC_COMMIT() asm volatile("cp.async.commit_group;" ::: "memory")
#define CPASYNC_WAIT0()  asm volatile("cp.async.wait_group 0;" ::: "memory")

// Issue cp.async for one 128x128 fp32 Z tile into P (linear: row r at r*512).
__device__ __forceinline__ void cpasync_tile(uint32_t Pu, const float* __restrict__ Z,
                                             int m0, int M, int tid) {
#pragma unroll
    for (int i = 0; i < 16; i++) {
        int c = tid + i * 256;        // 0..4095 16B chunks
        int r = c >> 5;
        int q = c & 31;
        int gr = m0 + r;
        unsigned sz = (gr < M) ? 16u : 0u;
        int grc = gr < M ? gr : (M - 1);
        const float* src = Z + (size_t)grc * 128 + q * 4;
        cpasync16(Pu + r * 512 + q * 16, src, sz);
    }
    CPASYNC_COMMIT();
}

// Convert fp32 tile in P (linear) -> fp16 tile in A (pchunk swizzle).
__device__ __forceinline__ void convert_tile(const char* P, char* A, int tid) {
#pragma unroll
    for (int i = 0; i < 16; i++) {
        int c = tid + i * 256;
        int r = c >> 5;
        int q = c & 31;
        float4 v = *(const float4*)(P + r * 512 + q * 16);
        __half2 h0 = __floats2half2_rn(v.x, v.y);
        __half2 h1 = __floats2half2_rn(v.z, v.w);
        uint2 pk;
        pk.x = *(uint32_t*)&h0; pk.y = *(uint32_t*)&h1;
        *(uint2*)(A + r * 256 + pchunk(q >> 1, r) * 16 + (q & 1) * 8) = pk;
    }
}

// MMA over one 128x128 A buffer.
__device__ __forceinline__ void tile_compute(
    float acc[2][8][4], uint32_t Acur, uint32_t Bu,
    int wr, int wc, int g, int idx)
{
#pragma unroll
    for (int mt = 0; mt < 2; mt++)
#pragma unroll
        for (int j = 0; j < 8; j++)
#pragma unroll
            for (int q = 0; q < 4; q++) acc[mt][j][q] = 0.f;

#pragma unroll
    for (int kk = 0; kk < 8; kk++) {
        uint32_t a[2][4];
#pragma unroll
        for (int mt = 0; mt < 2; mt++) {
            int ar  = wr + mt * 16 + (g & 1) * 8 + idx;
            int akc = kk * 2 + (g >> 1);
            ldm_x4(a[mt][0], a[mt][1], a[mt][2], a[mt][3],
                   Acur + ar * 256 + pchunk(akc, ar) * 16);
        }
#pragma unroll
        for (int jj = 0; jj < 4; jj++) {
            int bn  = wc + jj * 16 + (g >> 1) * 8 + idx;
            int bkc = kk * 2 + (g & 1);
            uint32_t b0, b1x, b2, b3;
            ldm_x4(b0, b1x, b2, b3, Bu + bn * 256 + pchunk(bkc, bn) * 16);
#pragma unroll
            for (int mt = 0; mt < 2; mt++) {
                mma_f16(acc[mt][2 * jj],     a[mt][0], a[mt][1], a[mt][2], a[mt][3], b0, b1x);
                mma_f16(acc[mt][2 * jj + 1], a[mt][0], a[mt][1], a[mt][2], a[mt][3], b2, b3);
            }
        }
    }
}

// Epilogue: scale (+C), stage fp16 tile into `stage` smem, coalesced STG.
__device__ __forceinline__ void tile_epilogue(
    float acc[2][8][4], char* stage, __half* __restrict__ out, int m0, int M,
    const float* sS, const float* sC,
    int tid, int wr, int wc, int t, int qr)
{
#pragma unroll
    for (int mt = 0; mt < 2; mt++) {
#pragma unroll
        for (int j = 0; j < 8; j++) {
            int n0 = wc + j * 8 + 2 * t;
            int ch = (wc >> 3) + j;
            float s0 = sS[n0], s1 = sS[n0 + 1];
            float c0 = sC[n0], c1 = sC[n0 + 1];
            int r0 = wr + mt * 16 + qr;
            int r1 = r0 + 8;
            __half2 h0 = __floats2half2_rn(fmaf(acc[mt][j][0], s0, c0),
                                           fmaf(acc[mt][j][1], s1, c1));
            __half2 h1 = __floats2half2_rn(fmaf(acc[mt][j][2], s0, c0),
                                           fmaf(acc[mt][j][3], s1, c1));
            *(__half2*)(stage + r0 * 256 + ((ch ^ (r0 & 7)) * 16) + 4 * t) = h0;
            *(__half2*)(stage + r1 * 256 + ((ch ^ (r1 & 7)) * 16) + 4 * t) = h1;
        }
    }
    __syncthreads();
#pragma unroll
    for (int pass = 0; pass < 8; pass++) {
        int i   = tid + pass * 256;
        int row = i >> 4;
        int ch  = i & 15;
        uint4 v = *(uint4*)(stage + row * 256 + ((ch ^ (row & 7)) * 16));
        int gr = m0 + row;
        if (gr < M)
            *(uint4*)(out + (size_t)gr * 128 + ch * 8) = v;
    }
}

// ---------------------------------------------------------------------------
// fp16 HMMA GEMM, cp.async-pipelined: 8 m-tiles per CTA (1024 rows), one W1
// fill, single wave at 1 CTA/SM (128 KB smem). Tile t+1's fp32 fill streams
// into P via cp.async while tile t computes. Ends with PDL signal.
// ---------------------------------------------------------------------------
__global__ void __launch_bounds__(256, 1)
gemm_mma(const float* __restrict__ zu, int Mu,
         const float* __restrict__ zf, int Mf,
         const float* __restrict__ W1,
         const float* __restrict__ gamma, const float* __restrict__ rvar,
         const float* __restrict__ b1, const float* __restrict__ beta,
         const float* __restrict__ rmean,
         __half* __restrict__ Uh, __half* __restrict__ Fh, int ctas_u)
{
    extern __shared__ char smem[];     // B:[0,32K) A:[32K,64K) P:[64K,128K)
    char* Bb = smem;
    char* Ab = smem + 32768;
    char* Pb = smem + 65536;
    __shared__ float sS[128];
    __shared__ float sC[128];

    int bid = blockIdx.x;
    const float* Z; int M; int koff; __half* out; bool isU;
    if (bid < ctas_u) { Z = zu; M = Mu; koff = 0;   out = Uh; isU = true; }
    else              { Z = zf; M = Mf; koff = 128; out = Fh; isU = false; bid -= ctas_u; }
    const int mbase = bid * ROWS_PER_CTA;

    const int tid  = threadIdx.x;
    const int wrp  = tid >> 5;
    const int lane = tid & 31;

    if (tid < 128) {
        float s = gamma[tid] * rsqrtf(rvar[tid] + EPSV);
        sS[tid] = s;
        sC[tid] = isU ? (b1[tid] * s + beta[tid] - rmean[tid] * s) : 0.f;
    }

    const uint32_t Bu = smem_u32(Bb);
    const uint32_t Au = smem_u32(Ab);
    const uint32_t Pu = smem_u32(Pb);

    // kick off tile 0's async fill immediately
    cpasync_tile(Pu, Z, mbase, M, tid);

    // ---- fill B once (direct LDG + convert) ----
    {
        const int kc = tid & 15;
        const int rb = tid >> 4;
#pragma unroll
        for (int pass = 0; pass < 8; pass++) {
            int r = rb + pass * 16;
            int pc16 = pchunk(kc, r) * 16;
            float4 bl = *(const float4*)(W1 + (size_t)r * 256 + koff + kc * 8);
            float4 bh = *(const float4*)(W1 + (size_t)r * 256 + koff + kc * 8 + 4);
            __half2 b0 = __floats2half2_rn(bl.x, bl.y);
            __half2 b1h = __floats2half2_rn(bl.z, bl.w);
            __half2 b2 = __floats2half2_rn(bh.x, bh.y);
            __half2 b3 = __floats2half2_rn(bh.z, bh.w);
            uint4 pb;
            pb.x = *(uint32_t*)&b0; pb.y = *(uint32_t*)&b1h;
            pb.z = *(uint32_t*)&b2; pb.w = *(uint32_t*)&b3;
            *(uint4*)(Bb + r * 256 + pc16) = pb;
        }
    }

    const int g   = lane >> 3;
    const int idx = lane & 7;
    const int wr  = (wrp & 3) * 32;
    const int wc  = (wrp >> 2) * 64;
    const int t   = lane & 3;
    const int qr  = lane >> 2;

    float acc[2][8][4];

#pragma unroll 1
    for (int tile = 0; tile < TILES_PER_CTA; tile++) {
        const int m0 = mbase + tile * 128;
        if (m0 >= M) break;

        CPASYNC_WAIT0();                  // this thread's pending tile copy done
        __syncthreads();                  // all threads' copies done; B ready too

        convert_tile(Pb, Ab, tid);        // P(fp32) -> A(fp16, swizzled)
        __syncthreads();                  // P free, A fully written

        const int mnext = m0 + 128;
        if (tile + 1 < TILES_PER_CTA && mnext < M)
            cpasync_tile(Pu, Z, mnext, M, tid);   // overlap with compute

        tile_compute(acc, Au, Bu, wr, wc, g, idx);
        __syncthreads();                  // MMA reads of A done

        tile_epilogue(acc, Ab, out, m0, M, sS, sC, tid, wr, wc, t, qr);
        __syncthreads();                  // stage reads done before next convert
    }

    // PDL: table writes for this CTA are done and flushed.
    __threadfence();
    asm volatile("griddepcontrol.launch_dependents;");
}

// ---------------------------------------------------------------------------
// Edge kernel (PDL consumer, unchanged — at chip LTS cap): 4 edges/warp,
// fp16 math, batched indices, double-buffered gathers.
// ---------------------------------------------------------------------------
__global__ void __launch_bounds__(256)
edge_kernel(const __half* __restrict__ U, const __half* __restrict__ F,
            const void* __restrict__ rowp, const void* __restrict__ colp,
            const float* __restrict__ W2, const float* __restrict__ b2,
            float* __restrict__ out, int E, int n_users, int n_foods)
{
    __shared__ __half2 sWh[64];
    __shared__ int s_is64;
    int tid = threadIdx.x;
    if (tid < 64) {
        float2 w2 = ((const float2*)W2)[tid];
        sWh[tid] = __floats2half2_rn(w2.x, w2.y);
    }
    if (tid < 32) {
        unsigned int v = ((const unsigned int*)rowp)[2 * tid + 1];
        unsigned int any = __ballot_sync(0xffffffffu, v != 0u);
        if (tid == 0) s_is64 = (any == 0u) ? 1 : 0;
    }
    __syncthreads();

    const int lane = tid & 31;
    const int sub  = lane & 7;
    const int g    = lane >> 3;

    __half2 w[8];
#pragma unroll
    for (int i = 0; i < 8; i++) w[i] = sWh[sub * 8 + i];
    const __half2 z2 = __half2half2(__ushort_as_half(0));

    const int warp = blockIdx.x * 8 + (tid >> 5);
    const int nw = gridDim.x * 8;
    const int is64 = s_is64;
    const float bias = b2[0] + 0.1f;

    const int*       row32 = (const int*)rowp;
    const int*       col32 = (const int*)colp;
    const long long* row64 = (const long long*)rowp;
    const long long* col64 = (const long long*)colp;
    const uint4* U4 = (const uint4*)U;
    const uint4* F4 = (const uint4*)F;

    bool waited = false;
    for (int base = warp * 32; base < E; base += nw * 32) {
        int myE = base + lane;
        int mi = myE < E ? myE : (E - 1);
        int ri, ci;
        if (is64) { ri = (int)row64[mi]; ci = (int)col64[mi]; }
        else      { ri = row32[mi];      ci = col32[mi]; }
        ri = min(max(ri, 0), n_users - 1);
        ci = min(max(ci, 0), n_foods - 1);

        if (!waited) {
            asm volatile("griddepcontrol.wait;" ::: "memory");
            waited = true;
        }

        uint4 bu0[2], bu1[2], bf0[2], bf1[2];
        {
            int rr = __shfl_sync(0xffffffffu, ri, g);
            int cc = __shfl_sync(0xffffffffu, ci, g);
            size_t ub = (size_t)rr * 16 + sub * 2;
            size_t fb = (size_t)cc * 16 + sub * 2;
            bu0[0] = U4[ub]; bu1[0] = U4[ub + 1];
            bf0[0] = F4[fb]; bf1[0] = F4[fb + 1];
        }

#pragma unroll
        for (int it = 0; it < 8; it++) {
            int cur = it & 1, nxt = cur ^ 1;
            if (it < 7) {
                int j2 = (it + 1) * 4 + g;
                int rr = __shfl_sync(0xffffffffu, ri, j2);
                int cc = __shfl_sync(0xffffffffu, ci, j2);
                size_t ub = (size_t)rr * 16 + sub * 2;
                size_t fb = (size_t)cc * 16 + sub * 2;
                bu0[nxt] = U4[ub]; bu1[nxt] = U4[ub + 1];
                bf0[nxt] = F4[fb]; bf1[nxt] = F4[fb + 1];
            }

            __half2 acc0 = z2, acc1 = z2;
#pragma unroll
            for (int q = 0; q < 4; q++) {
                uint32_t uq = (&bu0[cur].x)[q], fq = (&bf0[cur].x)[q];
                __half2 h = __hmax2(__hadd2(*(__half2*)&uq, *(__half2*)&fq), z2);
                if (q & 1) acc1 = __hfma2(h, w[q], acc1);
                else       acc0 = __hfma2(h, w[q], acc0);
            }
#pragma unroll
            for (int q = 0; q < 4; q++) {
                uint32_t uq = (&bu1[cur].x)[q], fq = (&bf1[cur].x)[q];
                __half2 h = __hmax2(__hadd2(*(__half2*)&uq, *(__half2*)&fq), z2);
                if (q & 1) acc1 = __hfma2(h, w[q + 4], acc1);
                else       acc0 = __hfma2(h, w[q + 4], acc0);
            }
            float2 dv = __half22float2(__hadd2(acc0, acc1));
            float dot = dv.x + dv.y;

            dot += __shfl_xor_sync(0xffffffffu, dot, 4);
            dot += __shfl_xor_sync(0xffffffffu, dot, 2);
            dot += __shfl_xor_sync(0xffffffffu, dot, 1);

            int e = base + it * 4 + g;
            if (sub == 0 && e < E)
                out[e] = 1.f / (1.f + __expf(-(dot + bias)));
        }
    }
}

// ---------------------------------------------------------------------------
// kernel_launch
// Inputs: z_user, z_food, row, col, W1, b1, gamma, beta, rmean, rvar, W2, b2
// ---------------------------------------------------------------------------
extern "C" void kernel_launch(void* const* d_in, const int* in_sizes, int n_in,
                              void* d_out, int out_size)
{
    const float* z_user = (const float*)d_in[0];
    const float* z_food = (const float*)d_in[1];
    const void*  row    = d_in[2];
    const void*  col    = d_in[3];
    const float* W1     = (const float*)d_in[4];
    const float* b1     = (const float*)d_in[5];
    const float* gamma  = (const float*)d_in[6];
    const float* beta   = (const float*)d_in[7];
    const float* rmean  = (const float*)d_in[8];
    const float* rvar   = (const float*)d_in[9];
    const float* W2     = (const float*)d_in[10];
    const float* b2     = (const float*)d_in[11];
    float*       out    = (float*)d_out;

    int n_users = in_sizes[0] / 128;
    int n_foods = in_sizes[1] / 128;
    int E       = in_sizes[2];
    if (n_users > NUSERS_MAX) n_users = NUSERS_MAX;
    if (n_foods > NFOODS_MAX) n_foods = NFOODS_MAX;

    __half *pU = nullptr, *pF = nullptr;
    cudaGetSymbolAddress((void**)&pU, g_Uh);
    cudaGetSymbolAddress((void**)&pF, g_Fh);

    int ctas_u = (n_users + ROWS_PER_CTA - 1) / ROWS_PER_CTA;
    int ctas_f = (n_foods + ROWS_PER_CTA - 1) / ROWS_PER_CTA;
    int smem = 131072;   // B 32K + A 32K + P 64K -> 1 CTA/SM
    cudaFuncSetAttribute(gemm_mma, cudaFuncAttributeMaxDynamicSharedMemorySize, smem);
    gemm_mma<<<ctas_u + ctas_f, 256, smem>>>(z_user, n_users, z_food, n_foods,
                                             W1, gamma, rvar, b1, beta, rmean,
                                             pU, pF, ctas_u);

    // Edge kernel with programmatic dependent launch.
    cudaLaunchConfig_t cfg = {};
    cfg.gridDim  = dim3(148 * 8, 1, 1);
    cfg.blockDim = dim3(256, 1, 1);
    cfg.dynamicSmemBytes = 0;
    cudaLaunchAttribute attrs[1];
    attrs[0].id = cudaLaunchAttributeProgrammaticStreamSerialization;
    attrs[0].val.programmaticStreamSerializationAllowed = 1;
    cfg.attrs = attrs;
    cfg.numAttrs = 1;
    cudaError_t err = cudaLaunchKernelEx(&cfg, edge_kernel,
                                         (const __half*)pU, (const __half*)pF,
                                         row, col, W2, b2, out,
                                         E, n_users, n_foods);
    if (err != cudaSuccess) {
        edge_kernel<<<148 * 8, 256>>>(pU, pF, row, col, W2, b2, out,
                                      E, n_users, n_foods);
    }
}